// round 1
// baseline (speedup 1.0000x reference)
#include <cuda_runtime.h>
#include <cstdint>
#include <cstddef>

// Problem constants
#define BATCH 4
#define SLEN  2048
#define DIM   1024

// GEMM tiling
#define BM 128
#define BN 128
#define BK 16

// Scratch (device globals — no allocation allowed in kernel_launch)
__device__ float g_Q[(size_t)BATCH * SLEN * DIM];
__device__ float g_K[(size_t)BATCH * SLEN * DIM];
__device__ float g_V[(size_t)BATCH * SLEN * DIM];
__device__ float g_P[(size_t)BATCH * SLEN * SLEN];

// ---------------------------------------------------------------------------
// C = A @ B  (row-major), 128x128x16 tile, 256 threads, 8x8 micro-tile.
// Optional per-batch strides (grid.z) and causal k-bound for the PV GEMM:
// when causal!=0, the K-loop stops at (blockIdx.y+1)*BM (q-tile upper bound).
// All dims are multiples of the tile sizes for this problem -> no bounds checks.
// ---------------------------------------------------------------------------
__global__ void __launch_bounds__(256)
gemm_nn(const float* __restrict__ A, const float* __restrict__ B,
        float* __restrict__ C, int K, int lda, int ldb, int ldc,
        size_t sA, size_t sB, size_t sC, int causal)
{
    const int z = blockIdx.z;
    A += (size_t)z * sA;
    B += (size_t)z * sB;
    C += (size_t)z * sC;

    const int m0 = blockIdx.y * BM;
    const int n0 = blockIdx.x * BN;
    int kEnd = causal ? (int)((blockIdx.y + 1) * BM) : K;
    if (kEnd > K) kEnd = K;

    __shared__ float As[BK][BM];
    __shared__ float Bs[BK][BN];

    const int tid = threadIdx.x;
    const int ty = tid >> 4;   // 0..15
    const int tx = tid & 15;   // 0..15

    float acc[8][8];
#pragma unroll
    for (int i = 0; i < 8; i++)
#pragma unroll
        for (int j = 0; j < 8; j++) acc[i][j] = 0.0f;

    for (int k0 = 0; k0 < kEnd; k0 += BK) {
        // Load A tile [BM x BK], store transposed As[k][m]
#pragma unroll
        for (int i = 0; i < 2; i++) {
            int f = tid + i * 256;          // 0..511 float4s
            int r = f >> 2;                 // row in tile (0..127)
            int c4 = f & 3;                 // float4 within row
            float4 v = *(const float4*)(A + (size_t)(m0 + r) * lda + k0 + c4 * 4);
            As[c4 * 4 + 0][r] = v.x;
            As[c4 * 4 + 1][r] = v.y;
            As[c4 * 4 + 2][r] = v.z;
            As[c4 * 4 + 3][r] = v.w;
        }
        // Load B tile [BK x BN], already k-major
#pragma unroll
        for (int i = 0; i < 2; i++) {
            int f = tid + i * 256;
            int r = f >> 5;                 // k row (0..15)
            int c4 = f & 31;                // float4 within row
            *(float4*)&Bs[r][c4 * 4] =
                *(const float4*)(B + (size_t)(k0 + r) * ldb + n0 + c4 * 4);
        }
        __syncthreads();

#pragma unroll
        for (int kk = 0; kk < BK; kk++) {
            float a[8], b[8];
            *(float4*)(a)     = *(const float4*)&As[kk][ty * 8];
            *(float4*)(a + 4) = *(const float4*)&As[kk][ty * 8 + 4];
            *(float4*)(b)     = *(const float4*)&Bs[kk][tx * 8];
            *(float4*)(b + 4) = *(const float4*)&Bs[kk][tx * 8 + 4];
#pragma unroll
            for (int i = 0; i < 8; i++)
#pragma unroll
                for (int j = 0; j < 8; j++)
                    acc[i][j] = fmaf(a[i], b[j], acc[i][j]);
        }
        __syncthreads();
    }

#pragma unroll
    for (int i = 0; i < 8; i++) {
        float* cp = C + (size_t)(m0 + ty * 8 + i) * ldc + n0 + tx * 8;
        *(float4*)(cp)     = make_float4(acc[i][0], acc[i][1], acc[i][2], acc[i][3]);
        *(float4*)(cp + 4) = make_float4(acc[i][4], acc[i][5], acc[i][6], acc[i][7]);
    }
}

// ---------------------------------------------------------------------------
// Scores: P[b,q,k] = scale * dot(Q[b,q,:], K[b,k,:])   (A @ B^T, causal)
// Blocks fully above the diagonal (bx > by) are skipped entirely.
// Diagonal blocks write only k <= q entries (softmax never reads k > q).
// ---------------------------------------------------------------------------
__global__ void __launch_bounds__(256)
scores_nt(const float* __restrict__ Q, const float* __restrict__ Km,
          float* __restrict__ P, int D, int Slen, float scale)
{
    const int bx = blockIdx.x, by = blockIdx.y, z = blockIdx.z;
    if (bx > by) return;  // fully masked tile

    const float* Ab = Q  + (size_t)z * Slen * D;
    const float* Bb = Km + (size_t)z * Slen * D;
    float*       Cb = P  + (size_t)z * Slen * Slen;

    const int m0 = by * BM;   // q
    const int n0 = bx * BN;   // k

    __shared__ float As[BK][BM];
    __shared__ float Bs[BK][BN];

    const int tid = threadIdx.x;
    const int ty = tid >> 4;
    const int tx = tid & 15;

    float acc[8][8];
#pragma unroll
    for (int i = 0; i < 8; i++)
#pragma unroll
        for (int j = 0; j < 8; j++) acc[i][j] = 0.0f;

    for (int k0 = 0; k0 < D; k0 += BK) {
#pragma unroll
        for (int i = 0; i < 2; i++) {
            int f = tid + i * 256;
            int r = f >> 2, c4 = f & 3;
            float4 v = *(const float4*)(Ab + (size_t)(m0 + r) * D + k0 + c4 * 4);
            As[c4 * 4 + 0][r] = v.x;
            As[c4 * 4 + 1][r] = v.y;
            As[c4 * 4 + 2][r] = v.z;
            As[c4 * 4 + 3][r] = v.w;
        }
        // B^T: tile rows index the k-sequence dimension (rows of K matrix)
#pragma unroll
        for (int i = 0; i < 2; i++) {
            int f = tid + i * 256;
            int r = f >> 2, c4 = f & 3;
            float4 v = *(const float4*)(Bb + (size_t)(n0 + r) * D + k0 + c4 * 4);
            Bs[c4 * 4 + 0][r] = v.x;
            Bs[c4 * 4 + 1][r] = v.y;
            Bs[c4 * 4 + 2][r] = v.z;
            Bs[c4 * 4 + 3][r] = v.w;
        }
        __syncthreads();

#pragma unroll
        for (int kk = 0; kk < BK; kk++) {
            float a[8], b[8];
            *(float4*)(a)     = *(const float4*)&As[kk][ty * 8];
            *(float4*)(a + 4) = *(const float4*)&As[kk][ty * 8 + 4];
            *(float4*)(b)     = *(const float4*)&Bs[kk][tx * 8];
            *(float4*)(b + 4) = *(const float4*)&Bs[kk][tx * 8 + 4];
#pragma unroll
            for (int i = 0; i < 8; i++)
#pragma unroll
                for (int j = 0; j < 8; j++)
                    acc[i][j] = fmaf(a[i], b[j], acc[i][j]);
        }
        __syncthreads();
    }

    const bool diag = (bx == by);
#pragma unroll
    for (int i = 0; i < 8; i++) {
        int gq = m0 + ty * 8 + i;
        float* cp = Cb + (size_t)gq * Slen + n0 + tx * 8;
        if (!diag) {
            *(float4*)(cp) = make_float4(acc[i][0] * scale, acc[i][1] * scale,
                                         acc[i][2] * scale, acc[i][3] * scale);
            *(float4*)(cp + 4) = make_float4(acc[i][4] * scale, acc[i][5] * scale,
                                             acc[i][6] * scale, acc[i][7] * scale);
        } else {
#pragma unroll
            for (int j = 0; j < 8; j++) {
                int gk = n0 + tx * 8 + j;
                if (gk <= gq) cp[j] = acc[i][j] * scale;
            }
        }
    }
}

// ---------------------------------------------------------------------------
// Row softmax over k in [0, q]; zero-pads (q, roundup128(q+1)) so the causal
// k-bounded PV GEMM can read whole 128-tiles safely.
// One 256-thread block per (b,q) row; row kept in registers (8 floats/thread).
// ---------------------------------------------------------------------------
__global__ void __launch_bounds__(256)
softmax_causal(float* __restrict__ P, int Slen)
{
    const int row = blockIdx.x;             // 0 .. B*SLEN-1
    const int q = row & (Slen - 1);          // Slen is a power of two
    float* p = P + (size_t)row * Slen;
    const int L = q + 1;
    const int t = threadIdx.x;

    float v[8];
    float mx = -INFINITY;
#pragma unroll
    for (int i = 0; i < 8; i++) {
        int idx = t + i * 256;
        v[i] = (idx < L) ? p[idx] : -INFINITY;
        mx = fmaxf(mx, v[i]);
    }

    __shared__ float redm[8];
    __shared__ float reds[8];

#pragma unroll
    for (int o = 16; o; o >>= 1) mx = fmaxf(mx, __shfl_xor_sync(0xFFFFFFFFu, mx, o));
    if ((t & 31) == 0) redm[t >> 5] = mx;
    __syncthreads();
    float m = redm[0];
#pragma unroll
    for (int i = 1; i < 8; i++) m = fmaxf(m, redm[i]);

    float s = 0.0f;
#pragma unroll
    for (int i = 0; i < 8; i++) {
        float e = __expf(v[i] - m);   // expf(-inf - m) = 0 for masked lanes
        v[i] = e;
        s += e;
    }
#pragma unroll
    for (int o = 16; o; o >>= 1) s += __shfl_xor_sync(0xFFFFFFFFu, s, o);
    if ((t & 31) == 0) reds[t >> 5] = s;
    __syncthreads();
    float tot = 0.0f;
#pragma unroll
    for (int i = 0; i < 8; i++) tot += reds[i];
    const float inv = 1.0f / tot;

    const int pad = (L + 127) & ~127;   // zero up to tile boundary for PV GEMM
#pragma unroll
    for (int i = 0; i < 8; i++) {
        int idx = t + i * 256;
        if (idx < L)        p[idx] = v[i] * inv;
        else if (idx < pad) p[idx] = 0.0f;
    }
}

// ---------------------------------------------------------------------------
extern "C" void kernel_launch(void* const* d_in, const int* in_sizes, int n_in,
                              void* d_out, int out_size)
{
    const float* x  = (const float*)d_in[0];
    const float* Wq = (const float*)d_in[1];
    const float* Wk = (const float*)d_in[2];
    const float* Wv = (const float*)d_in[3];
    float* out = (float*)d_out;
    (void)in_sizes; (void)n_in; (void)out_size;

    float *Qp, *Kp, *Vp, *Pp;
    cudaGetSymbolAddress((void**)&Qp, g_Q);
    cudaGetSymbolAddress((void**)&Kp, g_K);
    cudaGetSymbolAddress((void**)&Vp, g_V);
    cudaGetSymbolAddress((void**)&Pp, g_P);

    const dim3 blk(256);

    // QKV projections: [B*S, D] @ [D, D]
    const dim3 g1(DIM / BN, (BATCH * SLEN) / BM);   // 8 x 64
    gemm_nn<<<g1, blk>>>(x, Wq, Qp, DIM, DIM, DIM, DIM, 0, 0, 0, 0);
    gemm_nn<<<g1, blk>>>(x, Wk, Kp, DIM, DIM, DIM, DIM, 0, 0, 0, 0);
    gemm_nn<<<g1, blk>>>(x, Wv, Vp, DIM, DIM, DIM, DIM, 0, 0, 0, 0);

    // Scores: per batch, [S, D] @ [S, D]^T with causal tile skipping + scale
    const dim3 g2(SLEN / BN, SLEN / BM, BATCH);     // 16 x 16 x 4
    scores_nt<<<g2, blk>>>(Qp, Kp, Pp, DIM, SLEN, 0.03125f /* 1/sqrt(1024) */);

    // Softmax over k<=q, zero-padded to 128-tile boundary
    softmax_causal<<<BATCH * SLEN, 256>>>(Pp, SLEN);

    // Out = P @ V, with causal k-bound per q-tile
    const dim3 g3(DIM / BN, SLEN / BM, BATCH);      // 8 x 16 x 4
    gemm_nn<<<g3, blk>>>(Pp, Vp, out, SLEN, SLEN, DIM, DIM,
                         (size_t)SLEN * SLEN, (size_t)SLEN * DIM,
                         (size_t)SLEN * DIM, 1);
}

// round 2
// speedup vs baseline: 1.0007x; 1.0007x over previous
#include <cuda_runtime.h>
#include <cstdint>
#include <cstddef>

// Problem constants
#define BATCH 4
#define SLEN  2048
#define DIM   1024

// GEMM tiling
#define BM 128
#define BN 128
#define BK 16

// Scratch (device globals — no allocation allowed in kernel_launch)
__device__ float g_Q[(size_t)BATCH * SLEN * DIM];
__device__ float g_K[(size_t)BATCH * SLEN * DIM];
__device__ float g_V[(size_t)BATCH * SLEN * DIM];
__device__ float g_P[(size_t)BATCH * SLEN * SLEN];

// ---------------------------------------------------------------------------
// C = A @ B  (row-major), 128x128x16 tile, 256 threads, 8x8 micro-tile.
// Optional per-batch strides (grid.z) and causal k-bound for the PV GEMM:
// when causal!=0, the K-loop stops at (blockIdx.y+1)*BM (q-tile upper bound).
// All dims are multiples of the tile sizes for this problem -> no bounds checks.
// ---------------------------------------------------------------------------
__global__ void __launch_bounds__(256)
gemm_nn(const float* __restrict__ A, const float* __restrict__ B,
        float* __restrict__ C, int K, int lda, int ldb, int ldc,
        size_t sA, size_t sB, size_t sC, int causal)
{
    const int z = blockIdx.z;
    A += (size_t)z * sA;
    B += (size_t)z * sB;
    C += (size_t)z * sC;

    const int m0 = blockIdx.y * BM;
    const int n0 = blockIdx.x * BN;
    int kEnd = causal ? (int)((blockIdx.y + 1) * BM) : K;
    if (kEnd > K) kEnd = K;

    __shared__ float As[BK][BM];
    __shared__ float Bs[BK][BN];

    const int tid = threadIdx.x;
    const int ty = tid >> 4;   // 0..15
    const int tx = tid & 15;   // 0..15

    float acc[8][8];
#pragma unroll
    for (int i = 0; i < 8; i++)
#pragma unroll
        for (int j = 0; j < 8; j++) acc[i][j] = 0.0f;

    for (int k0 = 0; k0 < kEnd; k0 += BK) {
        // Load A tile [BM x BK], store transposed As[k][m]
#pragma unroll
        for (int i = 0; i < 2; i++) {
            int f = tid + i * 256;          // 0..511 float4s
            int r = f >> 2;                 // row in tile (0..127)
            int c4 = f & 3;                 // float4 within row
            float4 v = *(const float4*)(A + (size_t)(m0 + r) * lda + k0 + c4 * 4);
            As[c4 * 4 + 0][r] = v.x;
            As[c4 * 4 + 1][r] = v.y;
            As[c4 * 4 + 2][r] = v.z;
            As[c4 * 4 + 3][r] = v.w;
        }
        // Load B tile [BK x BN], already k-major
#pragma unroll
        for (int i = 0; i < 2; i++) {
            int f = tid + i * 256;
            int r = f >> 5;                 // k row (0..15)
            int c4 = f & 31;                // float4 within row
            *(float4*)&Bs[r][c4 * 4] =
                *(const float4*)(B + (size_t)(k0 + r) * ldb + n0 + c4 * 4);
        }
        __syncthreads();

#pragma unroll
        for (int kk = 0; kk < BK; kk++) {
            float a[8], b[8];
            *(float4*)(a)     = *(const float4*)&As[kk][ty * 8];
            *(float4*)(a + 4) = *(const float4*)&As[kk][ty * 8 + 4];
            *(float4*)(b)     = *(const float4*)&Bs[kk][tx * 8];
            *(float4*)(b + 4) = *(const float4*)&Bs[kk][tx * 8 + 4];
#pragma unroll
            for (int i = 0; i < 8; i++)
#pragma unroll
                for (int j = 0; j < 8; j++)
                    acc[i][j] = fmaf(a[i], b[j], acc[i][j]);
        }
        __syncthreads();
    }

#pragma unroll
    for (int i = 0; i < 8; i++) {
        float* cp = C + (size_t)(m0 + ty * 8 + i) * ldc + n0 + tx * 8;
        *(float4*)(cp)     = make_float4(acc[i][0], acc[i][1], acc[i][2], acc[i][3]);
        *(float4*)(cp + 4) = make_float4(acc[i][4], acc[i][5], acc[i][6], acc[i][7]);
    }
}

// ---------------------------------------------------------------------------
// Scores: P[b,q,k] = scale * dot(Q[b,q,:], K[b,k,:])   (A @ B^T, causal)
// Blocks fully above the diagonal (bx > by) are skipped entirely.
// Diagonal blocks write only k <= q entries (softmax never reads k > q).
// ---------------------------------------------------------------------------
__global__ void __launch_bounds__(256)
scores_nt(const float* __restrict__ Q, const float* __restrict__ Km,
          float* __restrict__ P, int D, int Slen, float scale)
{
    const int bx = blockIdx.x, by = blockIdx.y, z = blockIdx.z;
    if (bx > by) return;  // fully masked tile

    const float* Ab = Q  + (size_t)z * Slen * D;
    const float* Bb = Km + (size_t)z * Slen * D;
    float*       Cb = P  + (size_t)z * Slen * Slen;

    const int m0 = by * BM;   // q
    const int n0 = bx * BN;   // k

    __shared__ float As[BK][BM];
    __shared__ float Bs[BK][BN];

    const int tid = threadIdx.x;
    const int ty = tid >> 4;
    const int tx = tid & 15;

    float acc[8][8];
#pragma unroll
    for (int i = 0; i < 8; i++)
#pragma unroll
        for (int j = 0; j < 8; j++) acc[i][j] = 0.0f;

    for (int k0 = 0; k0 < D; k0 += BK) {
#pragma unroll
        for (int i = 0; i < 2; i++) {
            int f = tid + i * 256;
            int r = f >> 2, c4 = f & 3;
            float4 v = *(const float4*)(Ab + (size_t)(m0 + r) * D + k0 + c4 * 4);
            As[c4 * 4 + 0][r] = v.x;
            As[c4 * 4 + 1][r] = v.y;
            As[c4 * 4 + 2][r] = v.z;
            As[c4 * 4 + 3][r] = v.w;
        }
        // B^T: tile rows index the k-sequence dimension (rows of K matrix)
#pragma unroll
        for (int i = 0; i < 2; i++) {
            int f = tid + i * 256;
            int r = f >> 2, c4 = f & 3;
            float4 v = *(const float4*)(Bb + (size_t)(n0 + r) * D + k0 + c4 * 4);
            Bs[c4 * 4 + 0][r] = v.x;
            Bs[c4 * 4 + 1][r] = v.y;
            Bs[c4 * 4 + 2][r] = v.z;
            Bs[c4 * 4 + 3][r] = v.w;
        }
        __syncthreads();

#pragma unroll
        for (int kk = 0; kk < BK; kk++) {
            float a[8], b[8];
            *(float4*)(a)     = *(const float4*)&As[kk][ty * 8];
            *(float4*)(a + 4) = *(const float4*)&As[kk][ty * 8 + 4];
            *(float4*)(b)     = *(const float4*)&Bs[kk][tx * 8];
            *(float4*)(b + 4) = *(const float4*)&Bs[kk][tx * 8 + 4];
#pragma unroll
            for (int i = 0; i < 8; i++)
#pragma unroll
                for (int j = 0; j < 8; j++)
                    acc[i][j] = fmaf(a[i], b[j], acc[i][j]);
        }
        __syncthreads();
    }

    const bool diag = (bx == by);
#pragma unroll
    for (int i = 0; i < 8; i++) {
        int gq = m0 + ty * 8 + i;
        float* cp = Cb + (size_t)gq * Slen + n0 + tx * 8;
        if (!diag) {
            *(float4*)(cp) = make_float4(acc[i][0] * scale, acc[i][1] * scale,
                                         acc[i][2] * scale, acc[i][3] * scale);
            *(float4*)(cp + 4) = make_float4(acc[i][4] * scale, acc[i][5] * scale,
                                             acc[i][6] * scale, acc[i][7] * scale);
        } else {
#pragma unroll
            for (int j = 0; j < 8; j++) {
                int gk = n0 + tx * 8 + j;
                if (gk <= gq) cp[j] = acc[i][j] * scale;
            }
        }
    }
}

// ---------------------------------------------------------------------------
// Row softmax over k in [0, q]; zero-pads (q, roundup128(q+1)) so the causal
// k-bounded PV GEMM can read whole 128-tiles safely.
// One 256-thread block per (b,q) row; row kept in registers (8 floats/thread).
// ---------------------------------------------------------------------------
__global__ void __launch_bounds__(256)
softmax_causal(float* __restrict__ P, int Slen)
{
    const int row = blockIdx.x;             // 0 .. B*SLEN-1
    const int q = row & (Slen - 1);          // Slen is a power of two
    float* p = P + (size_t)row * Slen;
    const int L = q + 1;
    const int t = threadIdx.x;

    float v[8];
    float mx = -INFINITY;
#pragma unroll
    for (int i = 0; i < 8; i++) {
        int idx = t + i * 256;
        v[i] = (idx < L) ? p[idx] : -INFINITY;
        mx = fmaxf(mx, v[i]);
    }

    __shared__ float redm[8];
    __shared__ float reds[8];

#pragma unroll
    for (int o = 16; o; o >>= 1) mx = fmaxf(mx, __shfl_xor_sync(0xFFFFFFFFu, mx, o));
    if ((t & 31) == 0) redm[t >> 5] = mx;
    __syncthreads();
    float m = redm[0];
#pragma unroll
    for (int i = 1; i < 8; i++) m = fmaxf(m, redm[i]);

    float s = 0.0f;
#pragma unroll
    for (int i = 0; i < 8; i++) {
        float e = __expf(v[i] - m);   // expf(-inf - m) = 0 for masked lanes
        v[i] = e;
        s += e;
    }
#pragma unroll
    for (int o = 16; o; o >>= 1) s += __shfl_xor_sync(0xFFFFFFFFu, s, o);
    if ((t & 31) == 0) reds[t >> 5] = s;
    __syncthreads();
    float tot = 0.0f;
#pragma unroll
    for (int i = 0; i < 8; i++) tot += reds[i];
    const float inv = 1.0f / tot;

    const int pad = (L + 127) & ~127;   // zero up to tile boundary for PV GEMM
#pragma unroll
    for (int i = 0; i < 8; i++) {
        int idx = t + i * 256;
        if (idx < L)        p[idx] = v[i] * inv;
        else if (idx < pad) p[idx] = 0.0f;
    }
}

// ---------------------------------------------------------------------------
extern "C" void kernel_launch(void* const* d_in, const int* in_sizes, int n_in,
                              void* d_out, int out_size)
{
    const float* x  = (const float*)d_in[0];
    const float* Wq = (const float*)d_in[1];
    const float* Wk = (const float*)d_in[2];
    const float* Wv = (const float*)d_in[3];
    float* out = (float*)d_out;
    (void)in_sizes; (void)n_in; (void)out_size;

    float *Qp, *Kp, *Vp, *Pp;
    cudaGetSymbolAddress((void**)&Qp, g_Q);
    cudaGetSymbolAddress((void**)&Kp, g_K);
    cudaGetSymbolAddress((void**)&Vp, g_V);
    cudaGetSymbolAddress((void**)&Pp, g_P);

    const dim3 blk(256);

    // QKV projections: [B*S, D] @ [D, D]
    const dim3 g1(DIM / BN, (BATCH * SLEN) / BM);   // 8 x 64
    gemm_nn<<<g1, blk>>>(x, Wq, Qp, DIM, DIM, DIM, DIM, 0, 0, 0, 0);
    gemm_nn<<<g1, blk>>>(x, Wk, Kp, DIM, DIM, DIM, DIM, 0, 0, 0, 0);
    gemm_nn<<<g1, blk>>>(x, Wv, Vp, DIM, DIM, DIM, DIM, 0, 0, 0, 0);

    // Scores: per batch, [S, D] @ [S, D]^T with causal tile skipping + scale
    const dim3 g2(SLEN / BN, SLEN / BM, BATCH);     // 16 x 16 x 4
    scores_nt<<<g2, blk>>>(Qp, Kp, Pp, DIM, SLEN, 0.03125f /* 1/sqrt(1024) */);

    // Softmax over k<=q, zero-padded to 128-tile boundary
    softmax_causal<<<BATCH * SLEN, 256>>>(Pp, SLEN);

    // Out = P @ V, with causal k-bound per q-tile
    const dim3 g3(DIM / BN, SLEN / BM, BATCH);      // 8 x 16 x 4
    gemm_nn<<<g3, blk>>>(Pp, Vp, out, SLEN, SLEN, DIM, DIM,
                         (size_t)SLEN * SLEN, (size_t)SLEN * DIM,
                         (size_t)SLEN * DIM, 1);
}

// round 4
// speedup vs baseline: 3.0543x; 3.0523x over previous
#include <cuda_runtime.h>
#include <cuda_bf16.h>
#include <cstdint>
#include <cstddef>

typedef __nv_bfloat16 bf16;

#define BATCH 4
#define SLEN  2048
#define DIN   1024
#define NTOK  (BATCH*SLEN)

// GEMM tile config
#define BM 128
#define BN 128
#define BK 64                       // K elems per stage (bf16) = 128B rows
#define MAT_BYTES (128*128)         // 128 rows x 128 bytes = 16KB per matrix
#define STAGE_BYTES (4*MAT_BYTES)   // Ahi, Alo, Bhi, Blo
#define SM_A_HI 0
#define SM_A_LO (1*MAT_BYTES)
#define SM_B_HI (2*MAT_BYTES)
#define SM_B_LO (3*MAT_BYTES)
#define SMEM_REQ (1024 + 2*STAGE_BYTES)

// ---------------- scratch (device globals; no allocs allowed) ----------------
__device__ bf16 g_Xhi[(size_t)NTOK*DIN];
__device__ bf16 g_Xlo[(size_t)NTOK*DIN];
__device__ bf16 g_WThi[3][(size_t)DIN*DIN];   // W^T, split
__device__ bf16 g_WTlo[3][(size_t)DIN*DIN];
__device__ bf16 g_Qhi[(size_t)NTOK*DIN];
__device__ bf16 g_Qlo[(size_t)NTOK*DIN];
__device__ bf16 g_Khi[(size_t)NTOK*DIN];
__device__ bf16 g_Klo[(size_t)NTOK*DIN];
__device__ bf16 g_VThi[(size_t)DIN*NTOK];     // V^T: [e][b*S+s]
__device__ bf16 g_VTlo[(size_t)DIN*NTOK];
__device__ float g_S[(size_t)BATCH*SLEN*SLEN];    // raw scores (unscaled)
__device__ bf16 g_Phi[(size_t)BATCH*SLEN*SLEN];
__device__ bf16 g_Plo[(size_t)BATCH*SLEN*SLEN];

// ---------------- helpers ----------------
__device__ __forceinline__ uint32_t smem_u32(const void* p) {
    return (uint32_t)__cvta_generic_to_shared(p);
}
#define CP_COMMIT() asm volatile("cp.async.commit_group;\n" ::: "memory")
#define CP_WAIT1()  asm volatile("cp.async.wait_group 1;\n" ::: "memory")
#define CP_WAIT0()  asm volatile("cp.async.wait_group 0;\n" ::: "memory")

__device__ __forceinline__ void ldsm4(uint32_t* r, uint32_t addr) {
    asm volatile("ldmatrix.sync.aligned.m8n8.x4.shared.b16 {%0,%1,%2,%3}, [%4];"
        : "=r"(r[0]), "=r"(r[1]), "=r"(r[2]), "=r"(r[3]) : "r"(addr));
}
__device__ __forceinline__ void mma_bf16(float* d, const uint32_t* a, const uint32_t* b) {
    asm volatile(
        "mma.sync.aligned.m16n8k16.row.col.f32.bf16.bf16.f32 "
        "{%0,%1,%2,%3}, {%4,%5,%6,%7}, {%8,%9}, {%0,%1,%2,%3};"
        : "+f"(d[0]), "+f"(d[1]), "+f"(d[2]), "+f"(d[3])
        : "r"(a[0]), "r"(a[1]), "r"(a[2]), "r"(a[3]), "r"(b[0]), "r"(b[1]));
}

// cp.async a [128 x 64 bf16] tile (128B rows) into SW128-swizzled smem
__device__ __forceinline__ void load_tile(const bf16* __restrict__ g, int ld,
                                          int row0, int k0, uint32_t sdst, int tid)
{
#pragma unroll 4
    for (int c = tid; c < 128 * 8; c += 256) {
        int r = c >> 3, col = c & 7;
        const void* src = (const void*)(g + (size_t)(row0 + r) * ld + k0 + col * 8);
        uint32_t dst = sdst + ((uint32_t)r << 7) + ((uint32_t)(col ^ (r & 7)) << 4);
        asm volatile("cp.async.cg.shared.global [%0], [%1], 16;\n" :: "r"(dst), "l"(src));
    }
}

// ---------------------------------------------------------------------------
// Split-bf16 3-pass warp-MMA GEMM: D[m][n] = sum_k A[m][k]*B[n][k]
// D = Ahi*Bhi + Ahi*Blo + Alo*Bhi (all K-major operands)
// mode 0: fp32 output; mode 1: split hi/lo bf16 output
// causal 0: none; 1: skip tiles above diagonal (scores); 2: kEnd=(by+1)*BM (PV)
// ---------------------------------------------------------------------------
__global__ void __launch_bounds__(256)
gemm3(const bf16* __restrict__ Ahi, const bf16* __restrict__ Alo,
      const bf16* __restrict__ Bhi, const bf16* __restrict__ Blo,
      int K, int lda, int ldb,
      long long sAz, long long sBz, long long sCz,
      float* __restrict__ Cf, bf16* __restrict__ Chi, bf16* __restrict__ Clo,
      int ldc, int mode, int causal)
{
    const int bx = blockIdx.x, by = blockIdx.y, z = blockIdx.z;
    const int m0 = by * BM, n0 = bx * BN;
    if (causal == 1 && n0 > m0 + (BM - 1)) return;

    const int kEnd = (causal == 2) ? (by + 1) * BM : K;
    const int nit = kEnd / BK;

    Ahi += (size_t)z * sAz;  Alo += (size_t)z * sAz;
    Bhi += (size_t)z * sBz;  Blo += (size_t)z * sBz;

    extern __shared__ char smem_raw[];
    const uint32_t sbase = (smem_u32(smem_raw) + 1023u) & ~1023u;

    const int tid = threadIdx.x;
    const int wid = tid >> 5, lid = tid & 31;
    const int warp_m = wid >> 1;        // 0..3  (32 rows each)
    const int warp_n = wid & 1;         // 0..1  (64 cols each)

    float acc[2][8][4];
#pragma unroll
    for (int i = 0; i < 2; i++)
#pragma unroll
        for (int j = 0; j < 8; j++)
#pragma unroll
            for (int q = 0; q < 4; q++) acc[i][j][q] = 0.0f;

    // ldmatrix address components (within a 128x128B swizzled matrix)
    // A: row = warp_m*32 + im*16 + (lid&15); c16 = kk*2 + (lid>>4)
    const int a_row_base = warp_m * 32 + (lid & 15);
    const int a_chalf = lid >> 4;
    // B: n = warp_n*64 + jn*16 + (lid>>4)*8 + (lid&7); c16 = kk*2 + ((lid>>3)&1)
    const int b_row_base = warp_n * 64 + (lid >> 4) * 8 + (lid & 7);
    const int b_chalf = (lid >> 3) & 1;

    // prologue: stage 0
    load_tile(Ahi, lda, m0, 0, sbase + SM_A_HI, tid);
    load_tile(Alo, lda, m0, 0, sbase + SM_A_LO, tid);
    load_tile(Bhi, ldb, n0, 0, sbase + SM_B_HI, tid);
    load_tile(Blo, ldb, n0, 0, sbase + SM_B_LO, tid);
    CP_COMMIT();

    for (int it = 0; it < nit; it++) {
        const int p = it & 1;
        if (it + 1 < nit) {
            const uint32_t sb = sbase + (p ^ 1) * STAGE_BYTES;
            const int k0 = (it + 1) * BK;
            load_tile(Ahi, lda, m0, k0, sb + SM_A_HI, tid);
            load_tile(Alo, lda, m0, k0, sb + SM_A_LO, tid);
            load_tile(Bhi, ldb, n0, k0, sb + SM_B_HI, tid);
            load_tile(Blo, ldb, n0, k0, sb + SM_B_LO, tid);
            CP_COMMIT();
            CP_WAIT1();
        } else {
            CP_WAIT0();
        }
        __syncthreads();

        const uint32_t sb = sbase + p * STAGE_BYTES;
#pragma unroll
        for (int kk = 0; kk < 4; kk++) {
            uint32_t ah[2][4], al[2][4];
#pragma unroll
            for (int im = 0; im < 2; im++) {
                const int row = a_row_base + im * 16;
                const int c16 = kk * 2 + a_chalf;
                const uint32_t off = ((uint32_t)row << 7) + ((uint32_t)(c16 ^ (row & 7)) << 4);
                ldsm4(ah[im], sb + SM_A_HI + off);
                ldsm4(al[im], sb + SM_A_LO + off);
            }
#pragma unroll
            for (int jn = 0; jn < 4; jn++) {
                uint32_t bh[4], bl[4];
                const int n = b_row_base + jn * 16;
                const int c16 = kk * 2 + b_chalf;
                const uint32_t off = ((uint32_t)n << 7) + ((uint32_t)(c16 ^ (n & 7)) << 4);
                ldsm4(bh, sb + SM_B_HI + off);
                ldsm4(bl, sb + SM_B_LO + off);
#pragma unroll
                for (int im = 0; im < 2; im++) {
#pragma unroll
                    for (int h = 0; h < 2; h++) {
                        float* d = acc[im][jn * 2 + h];
                        mma_bf16(d, ah[im], bh + 2 * h);
                        mma_bf16(d, ah[im], bl + 2 * h);
                        mma_bf16(d, al[im], bh + 2 * h);
                    }
                }
            }
        }
        __syncthreads();
    }

    // epilogue
    const int tq = lid >> 2;   // 0..7
    const int tr = lid & 3;    // 0..3
    const size_t cbase = (size_t)z * (size_t)sCz;
#pragma unroll
    for (int im = 0; im < 2; im++) {
#pragma unroll
        for (int j = 0; j < 8; j++) {
            const int r0 = m0 + warp_m * 32 + im * 16 + tq;
            const int c0 = n0 + warp_n * 64 + j * 8 + tr * 2;
            const float* d = acc[im][j];
            if (mode == 0) {
                *(float2*)(Cf + cbase + (size_t)r0 * ldc + c0)       = make_float2(d[0], d[1]);
                *(float2*)(Cf + cbase + (size_t)(r0 + 8) * ldc + c0) = make_float2(d[2], d[3]);
            } else {
#pragma unroll
                for (int rr = 0; rr < 2; rr++) {
                    float va = d[2 * rr], vb = d[2 * rr + 1];
                    bf16 ha = __float2bfloat16(va);
                    bf16 hb = __float2bfloat16(vb);
                    __nv_bfloat162 hv; hv.x = ha; hv.y = hb;
                    __nv_bfloat162 lv;
                    lv.x = __float2bfloat16(va - __bfloat162float(ha));
                    lv.y = __float2bfloat16(vb - __bfloat162float(hb));
                    const size_t o = cbase + (size_t)(r0 + 8 * rr) * ldc + c0;
                    *(uint32_t*)(Chi + o) = *(uint32_t*)&hv;
                    *(uint32_t*)(Clo + o) = *(uint32_t*)&lv;
                }
            }
        }
    }
}

// ---------------------------------------------------------------------------
// fp32 -> (hi, lo) bf16 split, elementwise (4 per thread)
// ---------------------------------------------------------------------------
__global__ void __launch_bounds__(256)
split_f32(const float* __restrict__ x, bf16* __restrict__ hi, bf16* __restrict__ lo, int n4)
{
    int i = blockIdx.x * 256 + threadIdx.x;
    if (i >= n4) return;
    float4 v = ((const float4*)x)[i];
    float f[4] = {v.x, v.y, v.z, v.w};
    bf16 h[4]; bf16 l[4];
#pragma unroll
    for (int j = 0; j < 4; j++) {
        h[j] = __float2bfloat16(f[j]);
        l[j] = __float2bfloat16(f[j] - __bfloat162float(h[j]));
    }
    ((uint2*)hi)[i] = *(uint2*)h;
    ((uint2*)lo)[i] = *(uint2*)l;
}

// ---------------------------------------------------------------------------
// W [DIN x DIN] fp32 -> W^T hi/lo bf16
// ---------------------------------------------------------------------------
__global__ void __launch_bounds__(256)
transpose_split(const float* __restrict__ W, bf16* __restrict__ Thi, bf16* __restrict__ Tlo)
{
    __shared__ float t[32][33];
    const int bx = blockIdx.x * 32, by = blockIdx.y * 32;
    const int x = threadIdx.x, y = threadIdx.y;   // 32 x 8
#pragma unroll
    for (int i = 0; i < 32; i += 8)
        t[y + i][x] = W[(size_t)(by + y + i) * DIN + bx + x];
    __syncthreads();
#pragma unroll
    for (int i = 0; i < 32; i += 8) {
        float v = t[x][y + i];
        bf16 h = __float2bfloat16(v);
        bf16 l = __float2bfloat16(v - __bfloat162float(h));
        Thi[(size_t)(bx + y + i) * DIN + by + x] = h;
        Tlo[(size_t)(bx + y + i) * DIN + by + x] = l;
    }
}

// ---------------------------------------------------------------------------
// Softmax over k<=q of scale*S, emit split-bf16 P, zero-pad to 128 boundary
// ---------------------------------------------------------------------------
__global__ void __launch_bounds__(256)
softmax_split(const float* __restrict__ S, bf16* __restrict__ Phi, bf16* __restrict__ Plo,
              float scale)
{
    const int row = blockIdx.x;                // 0 .. B*SLEN-1
    const int q = row & (SLEN - 1);
    const float* p = S + (size_t)row * SLEN;
    const int L = q + 1;
    const int t = threadIdx.x;

    float v[8];
    float mx = -INFINITY;
#pragma unroll
    for (int i = 0; i < 8; i++) {
        int idx = t + i * 256;
        v[i] = (idx < L) ? p[idx] * scale : -INFINITY;
        mx = fmaxf(mx, v[i]);
    }

    __shared__ float redm[8];
    __shared__ float reds[8];

#pragma unroll
    for (int o = 16; o; o >>= 1) mx = fmaxf(mx, __shfl_xor_sync(0xFFFFFFFFu, mx, o));
    if ((t & 31) == 0) redm[t >> 5] = mx;
    __syncthreads();
    float m = redm[0];
#pragma unroll
    for (int i = 1; i < 8; i++) m = fmaxf(m, redm[i]);

    float s = 0.0f;
#pragma unroll
    for (int i = 0; i < 8; i++) {
        float e = __expf(v[i] - m);
        v[i] = e;
        s += e;
    }
#pragma unroll
    for (int o = 16; o; o >>= 1) s += __shfl_xor_sync(0xFFFFFFFFu, s, o);
    if ((t & 31) == 0) reds[t >> 5] = s;
    __syncthreads();
    float tot = 0.0f;
#pragma unroll
    for (int i = 0; i < 8; i++) tot += reds[i];
    const float inv = 1.0f / tot;

    bf16* ph = Phi + (size_t)row * SLEN;
    bf16* pl = Plo + (size_t)row * SLEN;
    const int pad = (L + 127) & ~127;
#pragma unroll
    for (int i = 0; i < 8; i++) {
        int idx = t + i * 256;
        if (idx < L) {
            float w = v[i] * inv;
            bf16 h = __float2bfloat16(w);
            ph[idx] = h;
            pl[idx] = __float2bfloat16(w - __bfloat162float(h));
        } else if (idx < pad) {
            ph[idx] = __float2bfloat16(0.0f);
            pl[idx] = __float2bfloat16(0.0f);
        }
    }
}

// ---------------------------------------------------------------------------
extern "C" void kernel_launch(void* const* d_in, const int* in_sizes, int n_in,
                              void* d_out, int out_size)
{
    const float* x  = (const float*)d_in[0];
    const float* Wq = (const float*)d_in[1];
    const float* Wk = (const float*)d_in[2];
    const float* Wv = (const float*)d_in[3];
    float* out = (float*)d_out;
    (void)in_sizes; (void)n_in; (void)out_size;

    cudaFuncSetAttribute(gemm3, cudaFuncAttributeMaxDynamicSharedMemorySize, SMEM_REQ);

    bf16 *Xhi, *Xlo, *WThi, *WTlo, *Qhi, *Qlo, *Khi, *Klo, *VThi, *VTlo, *Phi, *Plo;
    float *Sp;
    cudaGetSymbolAddress((void**)&Xhi, g_Xhi);
    cudaGetSymbolAddress((void**)&Xlo, g_Xlo);
    cudaGetSymbolAddress((void**)&WThi, g_WThi);
    cudaGetSymbolAddress((void**)&WTlo, g_WTlo);
    cudaGetSymbolAddress((void**)&Qhi, g_Qhi);
    cudaGetSymbolAddress((void**)&Qlo, g_Qlo);
    cudaGetSymbolAddress((void**)&Khi, g_Khi);
    cudaGetSymbolAddress((void**)&Klo, g_Klo);
    cudaGetSymbolAddress((void**)&VThi, g_VThi);
    cudaGetSymbolAddress((void**)&VTlo, g_VTlo);
    cudaGetSymbolAddress((void**)&Sp, g_S);
    cudaGetSymbolAddress((void**)&Phi, g_Phi);
    cudaGetSymbolAddress((void**)&Plo, g_Plo);

    const size_t WSTRIDE = (size_t)DIN * DIN;

    // 1) split x
    split_f32<<<(NTOK * DIN / 4) / 256, 256>>>(x, Xhi, Xlo, NTOK * DIN / 4);

    // 2) transpose + split the three weights
    {
        dim3 g(DIN / 32, DIN / 32), b(32, 8);
        transpose_split<<<g, b>>>(Wq, WThi + 0 * WSTRIDE, WTlo + 0 * WSTRIDE);
        transpose_split<<<g, b>>>(Wk, WThi + 1 * WSTRIDE, WTlo + 1 * WSTRIDE);
        transpose_split<<<g, b>>>(Wv, WThi + 2 * WSTRIDE, WTlo + 2 * WSTRIDE);
    }

    // 3) Q = x @ Wq, K = x @ Wk  (A = X [8192x1024], B = W^T [1024x1024])
    {
        dim3 g(DIN / BN, NTOK / BM, 1);   // 8 x 64
        gemm3<<<g, 256, SMEM_REQ>>>(Xhi, Xlo, WThi + 0 * WSTRIDE, WTlo + 0 * WSTRIDE,
                                    DIN, DIN, DIN, 0, 0, 0,
                                    nullptr, Qhi, Qlo, DIN, 1, 0);
        gemm3<<<g, 256, SMEM_REQ>>>(Xhi, Xlo, WThi + 1 * WSTRIDE, WTlo + 1 * WSTRIDE,
                                    DIN, DIN, DIN, 0, 0, 0,
                                    nullptr, Khi, Klo, DIN, 1, 0);
    }

    // 4) V^T = (x @ Wv)^T : A = Wv^T [1024x1024], B = X [8192x1024]
    {
        dim3 g(NTOK / BN, DIN / BM, 1);   // 64 x 8
        gemm3<<<g, 256, SMEM_REQ>>>(WThi + 2 * WSTRIDE, WTlo + 2 * WSTRIDE, Xhi, Xlo,
                                    DIN, DIN, DIN, 0, 0, 0,
                                    nullptr, VThi, VTlo, NTOK, 1, 0);
    }

    // 5) scores S[q][k] = Q . K per batch (unscaled), causal tile skip
    {
        dim3 g(SLEN / BN, SLEN / BM, BATCH);   // 16 x 16 x 4
        gemm3<<<g, 256, SMEM_REQ>>>(Qhi, Qlo, Khi, Klo,
                                    DIN, DIN, DIN,
                                    (long long)SLEN * DIN, (long long)SLEN * DIN,
                                    (long long)SLEN * SLEN,
                                    Sp, nullptr, nullptr, SLEN, 0, 1);
    }

    // 6) softmax + split P
    softmax_split<<<BATCH * SLEN, 256>>>(Sp, Phi, Plo, 0.03125f);

    // 7) out = P @ V : A = P [2048x2048] per batch, B = V^T (ldb = NTOK)
    {
        dim3 g(DIN / BN, SLEN / BM, BATCH);    // 8 x 16 x 4
        gemm3<<<g, 256, SMEM_REQ>>>(Phi, Plo, VThi, VTlo,
                                    SLEN, SLEN, NTOK,
                                    (long long)SLEN * SLEN, (long long)SLEN,
                                    (long long)SLEN * DIN,
                                    out, nullptr, nullptr, DIN, 0, 2);
    }
}

// round 5
// speedup vs baseline: 3.4703x; 1.1362x over previous
#include <cuda_runtime.h>
#include <cuda_bf16.h>
#include <cstdint>
#include <cstddef>

typedef __nv_bfloat16 bf16;

#define BATCH 4
#define SLEN  2048
#define DIN   1024
#define NTOK  (BATCH*SLEN)

// GEMM tile config: BM=64, BN=128, BK=64 -> stage 48KB, 2 stages, 2 CTAs/SM
#define BM 64
#define BN 128
#define BK 64
#define A_BYTES (64*128)            // 64 rows x 128B
#define B_BYTES (128*128)           // 128 rows x 128B
#define STAGE_BYTES (2*A_BYTES + 2*B_BYTES)   // 48KB
#define SM_A_HI 0
#define SM_A_LO (A_BYTES)
#define SM_B_HI (2*A_BYTES)
#define SM_B_LO (2*A_BYTES + B_BYTES)
#define SMEM_REQ (1024 + 2*STAGE_BYTES)

// ---------------- scratch (device globals; no allocs allowed) ----------------
__device__ bf16 g_Xhi[(size_t)NTOK*DIN];
__device__ bf16 g_Xlo[(size_t)NTOK*DIN];
__device__ bf16 g_WThi[3][(size_t)DIN*DIN];   // W^T, split
__device__ bf16 g_WTlo[3][(size_t)DIN*DIN];
__device__ bf16 g_Qhi[(size_t)NTOK*DIN];
__device__ bf16 g_Qlo[(size_t)NTOK*DIN];
__device__ bf16 g_Khi[(size_t)NTOK*DIN];
__device__ bf16 g_Klo[(size_t)NTOK*DIN];
__device__ bf16 g_VThi[(size_t)DIN*NTOK];     // V^T: [e][b*S+s]
__device__ bf16 g_VTlo[(size_t)DIN*NTOK];
__device__ float g_S[(size_t)BATCH*SLEN*SLEN];    // raw scores (unscaled)
__device__ bf16 g_Phi[(size_t)BATCH*SLEN*SLEN];
__device__ bf16 g_Plo[(size_t)BATCH*SLEN*SLEN];

// ---------------- helpers ----------------
__device__ __forceinline__ uint32_t smem_u32(const void* p) {
    return (uint32_t)__cvta_generic_to_shared(p);
}
#define CP_COMMIT() asm volatile("cp.async.commit_group;\n" ::: "memory")
#define CP_WAIT1()  asm volatile("cp.async.wait_group 1;\n" ::: "memory")
#define CP_WAIT0()  asm volatile("cp.async.wait_group 0;\n" ::: "memory")

__device__ __forceinline__ void ldsm4(uint32_t* r, uint32_t addr) {
    asm volatile("ldmatrix.sync.aligned.m8n8.x4.shared.b16 {%0,%1,%2,%3}, [%4];"
        : "=r"(r[0]), "=r"(r[1]), "=r"(r[2]), "=r"(r[3]) : "r"(addr));
}
__device__ __forceinline__ void mma_bf16(float* d, const uint32_t* a, const uint32_t* b) {
    asm volatile(
        "mma.sync.aligned.m16n8k16.row.col.f32.bf16.bf16.f32 "
        "{%0,%1,%2,%3}, {%4,%5,%6,%7}, {%8,%9}, {%0,%1,%2,%3};"
        : "+f"(d[0]), "+f"(d[1]), "+f"(d[2]), "+f"(d[3])
        : "r"(a[0]), "r"(a[1]), "r"(a[2]), "r"(a[3]), "r"(b[0]), "r"(b[1]));
}

// cp.async a [ROWS x 64 bf16] tile (128B rows) into swizzled smem; 128 threads
template<int ROWS>
__device__ __forceinline__ void load_tile(const bf16* __restrict__ g, int ld,
                                          int row0, int k0, uint32_t sdst, int tid)
{
#pragma unroll
    for (int c = tid; c < ROWS * 8; c += 128) {
        int r = c >> 3, col = c & 7;
        const void* src = (const void*)(g + (size_t)(row0 + r) * ld + k0 + col * 8);
        uint32_t dst = sdst + ((uint32_t)r << 7) + ((uint32_t)(col ^ (r & 7)) << 4);
        asm volatile("cp.async.cg.shared.global [%0], [%1], 16;\n" :: "r"(dst), "l"(src));
    }
}

// ---------------------------------------------------------------------------
// Split-bf16 3-pass warp-MMA GEMM: D[m][n] = sum_k A[m][k]*B[n][k]
// D = Ahi*Bhi + Ahi*Blo + Alo*Bhi (all K-major operands)
// mode 0: fp32 output; mode 1: split hi/lo bf16 output
// causal 0: none; 1: skip tiles above diagonal (scores); 2: kEnd=(by+1)*BM (PV)
// 128 threads, warps 2m x 2n, warp tile 32x64.
// ---------------------------------------------------------------------------
__global__ void __launch_bounds__(128)
gemm3(const bf16* __restrict__ Ahi, const bf16* __restrict__ Alo,
      const bf16* __restrict__ Bhi, const bf16* __restrict__ Blo,
      int K, int lda, int ldb,
      long long sAz, long long sBz, long long sCz,
      float* __restrict__ Cf, bf16* __restrict__ Chi, bf16* __restrict__ Clo,
      int ldc, int mode, int causal)
{
    const int bx = blockIdx.x, by = blockIdx.y, z = blockIdx.z;
    const int m0 = by * BM, n0 = bx * BN;
    if (causal == 1 && n0 > m0 + (BM - 1)) return;

    const int kEnd = (causal == 2) ? (by + 1) * BM : K;
    const int nit = kEnd / BK;

    Ahi += (size_t)z * sAz;  Alo += (size_t)z * sAz;
    Bhi += (size_t)z * sBz;  Blo += (size_t)z * sBz;

    extern __shared__ char smem_raw[];
    const uint32_t sbase = (smem_u32(smem_raw) + 1023u) & ~1023u;

    const int tid = threadIdx.x;
    const int wid = tid >> 5, lid = tid & 31;
    const int warp_m = wid >> 1;        // 0..1 (32 rows each)
    const int warp_n = wid & 1;         // 0..1 (64 cols each)

    float acc[2][8][4];
#pragma unroll
    for (int i = 0; i < 2; i++)
#pragma unroll
        for (int j = 0; j < 8; j++)
#pragma unroll
            for (int q = 0; q < 4; q++) acc[i][j][q] = 0.0f;

    // ldmatrix address components
    const int a_row_base = warp_m * 32 + (lid & 15);
    const int a_chalf = lid >> 4;
    const int b_row_base = warp_n * 64 + (lid >> 4) * 8 + (lid & 7);
    const int b_chalf = (lid >> 3) & 1;

    // prologue: stage 0
    load_tile<BM>(Ahi, lda, m0, 0, sbase + SM_A_HI, tid);
    load_tile<BM>(Alo, lda, m0, 0, sbase + SM_A_LO, tid);
    load_tile<BN>(Bhi, ldb, n0, 0, sbase + SM_B_HI, tid);
    load_tile<BN>(Blo, ldb, n0, 0, sbase + SM_B_LO, tid);
    CP_COMMIT();

    for (int it = 0; it < nit; it++) {
        const int p = it & 1;
        if (it + 1 < nit) {
            const uint32_t sb = sbase + (p ^ 1) * STAGE_BYTES;
            const int k0 = (it + 1) * BK;
            load_tile<BM>(Ahi, lda, m0, k0, sb + SM_A_HI, tid);
            load_tile<BM>(Alo, lda, m0, k0, sb + SM_A_LO, tid);
            load_tile<BN>(Bhi, ldb, n0, k0, sb + SM_B_HI, tid);
            load_tile<BN>(Blo, ldb, n0, k0, sb + SM_B_LO, tid);
            CP_COMMIT();
            CP_WAIT1();
        } else {
            CP_WAIT0();
        }
        __syncthreads();

        const uint32_t sb = sbase + p * STAGE_BYTES;
#pragma unroll
        for (int kk = 0; kk < 4; kk++) {
            uint32_t ah[2][4], al[2][4];
#pragma unroll
            for (int im = 0; im < 2; im++) {
                const int row = a_row_base + im * 16;
                const int c16 = kk * 2 + a_chalf;
                const uint32_t off = ((uint32_t)row << 7) + ((uint32_t)(c16 ^ (row & 7)) << 4);
                ldsm4(ah[im], sb + SM_A_HI + off);
                ldsm4(al[im], sb + SM_A_LO + off);
            }
#pragma unroll
            for (int jn = 0; jn < 4; jn++) {
                uint32_t bh[4], bl[4];
                const int n = b_row_base + jn * 16;
                const int c16 = kk * 2 + b_chalf;
                const uint32_t off = ((uint32_t)n << 7) + ((uint32_t)(c16 ^ (n & 7)) << 4);
                ldsm4(bh, sb + SM_B_HI + off);
                ldsm4(bl, sb + SM_B_LO + off);
#pragma unroll
                for (int im = 0; im < 2; im++) {
#pragma unroll
                    for (int h = 0; h < 2; h++) {
                        float* d = acc[im][jn * 2 + h];
                        mma_bf16(d, ah[im], bh + 2 * h);
                        mma_bf16(d, ah[im], bl + 2 * h);
                        mma_bf16(d, al[im], bh + 2 * h);
                    }
                }
            }
        }
        __syncthreads();
    }

    // epilogue
    const int tq = lid >> 2;   // 0..7
    const int tr = lid & 3;    // 0..3
    const size_t cbase = (size_t)z * (size_t)sCz;
#pragma unroll
    for (int im = 0; im < 2; im++) {
#pragma unroll
        for (int j = 0; j < 8; j++) {
            const int r0 = m0 + warp_m * 32 + im * 16 + tq;
            const int c0 = n0 + warp_n * 64 + j * 8 + tr * 2;
            const float* d = acc[im][j];
            if (mode == 0) {
                *(float2*)(Cf + cbase + (size_t)r0 * ldc + c0)       = make_float2(d[0], d[1]);
                *(float2*)(Cf + cbase + (size_t)(r0 + 8) * ldc + c0) = make_float2(d[2], d[3]);
            } else {
#pragma unroll
                for (int rr = 0; rr < 2; rr++) {
                    float va = d[2 * rr], vb = d[2 * rr + 1];
                    bf16 ha = __float2bfloat16(va);
                    bf16 hb = __float2bfloat16(vb);
                    __nv_bfloat162 hv; hv.x = ha; hv.y = hb;
                    __nv_bfloat162 lv;
                    lv.x = __float2bfloat16(va - __bfloat162float(ha));
                    lv.y = __float2bfloat16(vb - __bfloat162float(hb));
                    const size_t o = cbase + (size_t)(r0 + 8 * rr) * ldc + c0;
                    *(uint32_t*)(Chi + o) = *(uint32_t*)&hv;
                    *(uint32_t*)(Clo + o) = *(uint32_t*)&lv;
                }
            }
        }
    }
}

// ---------------------------------------------------------------------------
__global__ void __launch_bounds__(256)
split_f32(const float* __restrict__ x, bf16* __restrict__ hi, bf16* __restrict__ lo, int n4)
{
    int i = blockIdx.x * 256 + threadIdx.x;
    if (i >= n4) return;
    float4 v = ((const float4*)x)[i];
    float f[4] = {v.x, v.y, v.z, v.w};
    bf16 h[4]; bf16 l[4];
#pragma unroll
    for (int j = 0; j < 4; j++) {
        h[j] = __float2bfloat16(f[j]);
        l[j] = __float2bfloat16(f[j] - __bfloat162float(h[j]));
    }
    ((uint2*)hi)[i] = *(uint2*)h;
    ((uint2*)lo)[i] = *(uint2*)l;
}

// ---------------------------------------------------------------------------
__global__ void __launch_bounds__(256)
transpose_split(const float* __restrict__ W, bf16* __restrict__ Thi, bf16* __restrict__ Tlo)
{
    __shared__ float t[32][33];
    const int bx = blockIdx.x * 32, by = blockIdx.y * 32;
    const int x = threadIdx.x, y = threadIdx.y;   // 32 x 8
#pragma unroll
    for (int i = 0; i < 32; i += 8)
        t[y + i][x] = W[(size_t)(by + y + i) * DIN + bx + x];
    __syncthreads();
#pragma unroll
    for (int i = 0; i < 32; i += 8) {
        float v = t[x][y + i];
        bf16 h = __float2bfloat16(v);
        bf16 l = __float2bfloat16(v - __bfloat162float(h));
        Thi[(size_t)(bx + y + i) * DIN + by + x] = h;
        Tlo[(size_t)(bx + y + i) * DIN + by + x] = l;
    }
}

// ---------------------------------------------------------------------------
// Softmax over k<=q of scale*S, emit split-bf16 P, zero-pad to 64 boundary
// ---------------------------------------------------------------------------
__global__ void __launch_bounds__(256)
softmax_split(const float* __restrict__ S, bf16* __restrict__ Phi, bf16* __restrict__ Plo,
              float scale)
{
    const int row = blockIdx.x;                // 0 .. B*SLEN-1
    const int q = row & (SLEN - 1);
    const float* p = S + (size_t)row * SLEN;
    const int L = q + 1;
    const int t = threadIdx.x;

    float v[8];
    float mx = -INFINITY;
#pragma unroll
    for (int i = 0; i < 8; i++) {
        int idx = t + i * 256;
        v[i] = (idx < L) ? p[idx] * scale : -INFINITY;
        mx = fmaxf(mx, v[i]);
    }

    __shared__ float redm[8];
    __shared__ float reds[8];

#pragma unroll
    for (int o = 16; o; o >>= 1) mx = fmaxf(mx, __shfl_xor_sync(0xFFFFFFFFu, mx, o));
    if ((t & 31) == 0) redm[t >> 5] = mx;
    __syncthreads();
    float m = redm[0];
#pragma unroll
    for (int i = 1; i < 8; i++) m = fmaxf(m, redm[i]);

    float s = 0.0f;
#pragma unroll
    for (int i = 0; i < 8; i++) {
        float e = __expf(v[i] - m);
        v[i] = e;
        s += e;
    }
#pragma unroll
    for (int o = 16; o; o >>= 1) s += __shfl_xor_sync(0xFFFFFFFFu, s, o);
    if ((t & 31) == 0) reds[t >> 5] = s;
    __syncthreads();
    float tot = 0.0f;
#pragma unroll
    for (int i = 0; i < 8; i++) tot += reds[i];
    const float inv = 1.0f / tot;

    bf16* ph = Phi + (size_t)row * SLEN;
    bf16* pl = Plo + (size_t)row * SLEN;
    const int pad = (L + 63) & ~63;
#pragma unroll
    for (int i = 0; i < 8; i++) {
        int idx = t + i * 256;
        if (idx < L) {
            float w = v[i] * inv;
            bf16 h = __float2bfloat16(w);
            ph[idx] = h;
            pl[idx] = __float2bfloat16(w - __bfloat162float(h));
        } else if (idx < pad) {
            ph[idx] = __float2bfloat16(0.0f);
            pl[idx] = __float2bfloat16(0.0f);
        }
    }
}

// ---------------------------------------------------------------------------
extern "C" void kernel_launch(void* const* d_in, const int* in_sizes, int n_in,
                              void* d_out, int out_size)
{
    const float* x  = (const float*)d_in[0];
    const float* Wq = (const float*)d_in[1];
    const float* Wk = (const float*)d_in[2];
    const float* Wv = (const float*)d_in[3];
    float* out = (float*)d_out;
    (void)in_sizes; (void)n_in; (void)out_size;

    cudaFuncSetAttribute(gemm3, cudaFuncAttributeMaxDynamicSharedMemorySize, SMEM_REQ);

    bf16 *Xhi, *Xlo, *WThi, *WTlo, *Qhi, *Qlo, *Khi, *Klo, *VThi, *VTlo, *Phi, *Plo;
    float *Sp;
    cudaGetSymbolAddress((void**)&Xhi, g_Xhi);
    cudaGetSymbolAddress((void**)&Xlo, g_Xlo);
    cudaGetSymbolAddress((void**)&WThi, g_WThi);
    cudaGetSymbolAddress((void**)&WTlo, g_WTlo);
    cudaGetSymbolAddress((void**)&Qhi, g_Qhi);
    cudaGetSymbolAddress((void**)&Qlo, g_Qlo);
    cudaGetSymbolAddress((void**)&Khi, g_Khi);
    cudaGetSymbolAddress((void**)&Klo, g_Klo);
    cudaGetSymbolAddress((void**)&VThi, g_VThi);
    cudaGetSymbolAddress((void**)&VTlo, g_VTlo);
    cudaGetSymbolAddress((void**)&Sp, g_S);
    cudaGetSymbolAddress((void**)&Phi, g_Phi);
    cudaGetSymbolAddress((void**)&Plo, g_Plo);

    const size_t WSTRIDE = (size_t)DIN * DIN;

    // 1) split x
    split_f32<<<(NTOK * DIN / 4) / 256, 256>>>(x, Xhi, Xlo, NTOK * DIN / 4);

    // 2) transpose + split the three weights
    {
        dim3 g(DIN / 32, DIN / 32), b(32, 8);
        transpose_split<<<g, b>>>(Wq, WThi + 0 * WSTRIDE, WTlo + 0 * WSTRIDE);
        transpose_split<<<g, b>>>(Wk, WThi + 1 * WSTRIDE, WTlo + 1 * WSTRIDE);
        transpose_split<<<g, b>>>(Wv, WThi + 2 * WSTRIDE, WTlo + 2 * WSTRIDE);
    }

    // 3) Q = x @ Wq, K = x @ Wk
    {
        dim3 g(DIN / BN, NTOK / BM, 1);   // 8 x 128
        gemm3<<<g, 128, SMEM_REQ>>>(Xhi, Xlo, WThi + 0 * WSTRIDE, WTlo + 0 * WSTRIDE,
                                    DIN, DIN, DIN, 0, 0, 0,
                                    nullptr, Qhi, Qlo, DIN, 1, 0);
        gemm3<<<g, 128, SMEM_REQ>>>(Xhi, Xlo, WThi + 1 * WSTRIDE, WTlo + 1 * WSTRIDE,
                                    DIN, DIN, DIN, 0, 0, 0,
                                    nullptr, Khi, Klo, DIN, 1, 0);
    }

    // 4) V^T = (x @ Wv)^T : A = Wv^T [1024x1024], B = X [8192x1024]
    {
        dim3 g(NTOK / BN, DIN / BM, 1);   // 64 x 16
        gemm3<<<g, 128, SMEM_REQ>>>(WThi + 2 * WSTRIDE, WTlo + 2 * WSTRIDE, Xhi, Xlo,
                                    DIN, DIN, DIN, 0, 0, 0,
                                    nullptr, VThi, VTlo, NTOK, 1, 0);
    }

    // 5) scores S[q][k] = Q . K per batch (unscaled), causal tile skip
    {
        dim3 g(SLEN / BN, SLEN / BM, BATCH);   // 16 x 32 x 4
        gemm3<<<g, 128, SMEM_REQ>>>(Qhi, Qlo, Khi, Klo,
                                    DIN, DIN, DIN,
                                    (long long)SLEN * DIN, (long long)SLEN * DIN,
                                    (long long)SLEN * SLEN,
                                    Sp, nullptr, nullptr, SLEN, 0, 1);
    }

    // 6) softmax + split P
    softmax_split<<<BATCH * SLEN, 256>>>(Sp, Phi, Plo, 0.03125f);

    // 7) out = P @ V : A = P [2048x2048] per batch, B = V^T (ldb = NTOK)
    {
        dim3 g(DIN / BN, SLEN / BM, BATCH);    // 8 x 32 x 4
        gemm3<<<g, 128, SMEM_REQ>>>(Phi, Plo, VThi, VTlo,
                                    SLEN, SLEN, NTOK,
                                    (long long)SLEN * SLEN, (long long)SLEN,
                                    (long long)SLEN * DIN,
                                    out, nullptr, nullptr, DIN, 0, 2);
    }
}

// round 6
// speedup vs baseline: 3.5615x; 1.0263x over previous
#include <cuda_runtime.h>
#include <cuda_bf16.h>
#include <cstdint>
#include <cstddef>

typedef __nv_bfloat16 bf16;

#define BATCH 4
#define SLEN  2048
#define DIN   1024
#define NTOK  (BATCH*SLEN)

// GEMM tile config: BM=64, BN=128, BK=64 -> stage 48KB, 2 stages, 2 CTAs/SM
#define BM 64
#define BN 128
#define BK 64
#define A_BYTES (64*128)
#define B_BYTES (128*128)
#define STAGE_BYTES (2*A_BYTES + 2*B_BYTES)   // 48KB
#define SM_A_HI 0
#define SM_A_LO (A_BYTES)
#define SM_B_HI (2*A_BYTES)
#define SM_B_LO (2*A_BYTES + B_BYTES)
#define SMEM_REQ (1024 + 2*STAGE_BYTES)

// ---------------- scratch (device globals; no allocs allowed) ----------------
__device__ bf16 g_Xhi[(size_t)NTOK*DIN];
__device__ bf16 g_Xlo[(size_t)NTOK*DIN];
__device__ bf16 g_WThi[3][(size_t)DIN*DIN];   // W^T split; [0],[1] contiguous = QK merged B
__device__ bf16 g_WTlo[3][(size_t)DIN*DIN];
__device__ bf16 g_QKhi[(size_t)NTOK*2*DIN];   // interleaved: cols 0..1023=Q, 1024..2047=K
__device__ bf16 g_QKlo[(size_t)NTOK*2*DIN];
__device__ bf16 g_VThi[(size_t)DIN*NTOK];     // V^T: [e][b*S+s]
__device__ bf16 g_VTlo[(size_t)DIN*NTOK];
__device__ float g_S[(size_t)BATCH*SLEN*SLEN];    // raw scores (unscaled)
__device__ bf16 g_Phi[(size_t)BATCH*SLEN*SLEN];
__device__ bf16 g_Plo[(size_t)BATCH*SLEN*SLEN];

// ---------------- helpers ----------------
__device__ __forceinline__ uint32_t smem_u32(const void* p) {
    return (uint32_t)__cvta_generic_to_shared(p);
}
#define CP_COMMIT() asm volatile("cp.async.commit_group;\n" ::: "memory")
#define CP_WAIT1()  asm volatile("cp.async.wait_group 1;\n" ::: "memory")
#define CP_WAIT0()  asm volatile("cp.async.wait_group 0;\n" ::: "memory")

__device__ __forceinline__ void ldsm4(uint32_t* r, uint32_t addr) {
    asm volatile("ldmatrix.sync.aligned.m8n8.x4.shared.b16 {%0,%1,%2,%3}, [%4];"
        : "=r"(r[0]), "=r"(r[1]), "=r"(r[2]), "=r"(r[3]) : "r"(addr));
}
__device__ __forceinline__ void mma_bf16(float* d, const uint32_t* a, const uint32_t* b) {
    asm volatile(
        "mma.sync.aligned.m16n8k16.row.col.f32.bf16.bf16.f32 "
        "{%0,%1,%2,%3}, {%4,%5,%6,%7}, {%8,%9}, {%0,%1,%2,%3};"
        : "+f"(d[0]), "+f"(d[1]), "+f"(d[2]), "+f"(d[3])
        : "r"(a[0]), "r"(a[1]), "r"(a[2]), "r"(a[3]), "r"(b[0]), "r"(b[1]));
}

// cp.async a [ROWS x 64 bf16] tile (128B rows) into swizzled smem; 128 threads
template<int ROWS>
__device__ __forceinline__ void load_tile(const bf16* __restrict__ g, int ld,
                                          int row0, int k0, uint32_t sdst, int tid)
{
#pragma unroll
    for (int c = tid; c < ROWS * 8; c += 128) {
        int r = c >> 3, col = c & 7;
        const void* src = (const void*)(g + (size_t)(row0 + r) * ld + k0 + col * 8);
        uint32_t dst = sdst + ((uint32_t)r << 7) + ((uint32_t)(col ^ (r & 7)) << 4);
        asm volatile("cp.async.cg.shared.global [%0], [%1], 16;\n" :: "r"(dst), "l"(src));
    }
}

// ---------------------------------------------------------------------------
// Split-bf16 3-pass warp-MMA GEMM: D[m][n] = sum_k A[m][k]*B[n][k]
// D = Ahi*Bhi + Ahi*Blo + Alo*Bhi (all K-major operands)
// mode 0: fp32 output; mode 1: split hi/lo bf16 output
// causal 0: none; 1: skip tiles above diagonal (scores);
//        2: kEnd=(by+1)*BM (PV);
//        3: like 2 but with launch-order load-balancing remap of by
// 128 threads, warps 2m x 2n, warp tile 32x64.
// ---------------------------------------------------------------------------
__global__ void __launch_bounds__(128)
gemm3(const bf16* __restrict__ Ahi, const bf16* __restrict__ Alo,
      const bf16* __restrict__ Bhi, const bf16* __restrict__ Blo,
      int K, int lda, int ldb,
      long long sAz, long long sBz, long long sCz,
      float* __restrict__ Cf, bf16* __restrict__ Chi, bf16* __restrict__ Clo,
      int ldc, int mode, int causal)
{
    const int bx = blockIdx.x, z = blockIdx.z;
    int by = blockIdx.y;
    if (causal == 3) {   // interleave heavy (high-by) with light (low-by) CTAs
        const int n = gridDim.y;
        by = (by & 1) ? (n - 1 - (by >> 1)) : (by >> 1);
    }
    const int m0 = by * BM, n0 = bx * BN;
    if (causal == 1 && n0 > m0 + (BM - 1)) return;

    const int kEnd = (causal >= 2) ? (by + 1) * BM : K;
    const int nit = kEnd / BK;

    Ahi += (size_t)z * sAz;  Alo += (size_t)z * sAz;
    Bhi += (size_t)z * sBz;  Blo += (size_t)z * sBz;

    extern __shared__ char smem_raw[];
    const uint32_t sbase = (smem_u32(smem_raw) + 1023u) & ~1023u;

    const int tid = threadIdx.x;
    const int wid = tid >> 5, lid = tid & 31;
    const int warp_m = wid >> 1;        // 0..1 (32 rows each)
    const int warp_n = wid & 1;         // 0..1 (64 cols each)

    float acc[2][8][4];
#pragma unroll
    for (int i = 0; i < 2; i++)
#pragma unroll
        for (int j = 0; j < 8; j++)
#pragma unroll
            for (int q = 0; q < 4; q++) acc[i][j][q] = 0.0f;

    // ldmatrix address components
    const int a_row_base = warp_m * 32 + (lid & 15);
    const int a_chalf = lid >> 4;
    const int b_row_base = warp_n * 64 + (lid >> 4) * 8 + (lid & 7);
    const int b_chalf = (lid >> 3) & 1;

    // prologue: stage 0
    load_tile<BM>(Ahi, lda, m0, 0, sbase + SM_A_HI, tid);
    load_tile<BM>(Alo, lda, m0, 0, sbase + SM_A_LO, tid);
    load_tile<BN>(Bhi, ldb, n0, 0, sbase + SM_B_HI, tid);
    load_tile<BN>(Blo, ldb, n0, 0, sbase + SM_B_LO, tid);
    CP_COMMIT();

    for (int it = 0; it < nit; it++) {
        const int p = it & 1;
        if (it + 1 < nit) {
            const uint32_t sb = sbase + (p ^ 1) * STAGE_BYTES;
            const int k0 = (it + 1) * BK;
            load_tile<BM>(Ahi, lda, m0, k0, sb + SM_A_HI, tid);
            load_tile<BM>(Alo, lda, m0, k0, sb + SM_A_LO, tid);
            load_tile<BN>(Bhi, ldb, n0, k0, sb + SM_B_HI, tid);
            load_tile<BN>(Blo, ldb, n0, k0, sb + SM_B_LO, tid);
            CP_COMMIT();
            CP_WAIT1();
        } else {
            CP_WAIT0();
        }
        __syncthreads();

        const uint32_t sb = sbase + p * STAGE_BYTES;
#pragma unroll
        for (int kk = 0; kk < 4; kk++) {
            uint32_t ah[2][4], al[2][4];
#pragma unroll
            for (int im = 0; im < 2; im++) {
                const int row = a_row_base + im * 16;
                const int c16 = kk * 2 + a_chalf;
                const uint32_t off = ((uint32_t)row << 7) + ((uint32_t)(c16 ^ (row & 7)) << 4);
                ldsm4(ah[im], sb + SM_A_HI + off);
                ldsm4(al[im], sb + SM_A_LO + off);
            }
#pragma unroll
            for (int jn = 0; jn < 4; jn++) {
                uint32_t bh[4], bl[4];
                const int n = b_row_base + jn * 16;
                const int c16 = kk * 2 + b_chalf;
                const uint32_t off = ((uint32_t)n << 7) + ((uint32_t)(c16 ^ (n & 7)) << 4);
                ldsm4(bh, sb + SM_B_HI + off);
                ldsm4(bl, sb + SM_B_LO + off);
#pragma unroll
                for (int im = 0; im < 2; im++) {
#pragma unroll
                    for (int h = 0; h < 2; h++) {
                        float* d = acc[im][jn * 2 + h];
                        mma_bf16(d, ah[im], bh + 2 * h);
                        mma_bf16(d, ah[im], bl + 2 * h);
                        mma_bf16(d, al[im], bh + 2 * h);
                    }
                }
            }
        }
        __syncthreads();
    }

    // epilogue
    const int tq = lid >> 2;   // 0..7
    const int tr = lid & 3;    // 0..3
    const size_t cbase = (size_t)z * (size_t)sCz;
#pragma unroll
    for (int im = 0; im < 2; im++) {
#pragma unroll
        for (int j = 0; j < 8; j++) {
            const int r0 = m0 + warp_m * 32 + im * 16 + tq;
            const int c0 = n0 + warp_n * 64 + j * 8 + tr * 2;
            const float* d = acc[im][j];
            if (mode == 0) {
                *(float2*)(Cf + cbase + (size_t)r0 * ldc + c0)       = make_float2(d[0], d[1]);
                *(float2*)(Cf + cbase + (size_t)(r0 + 8) * ldc + c0) = make_float2(d[2], d[3]);
            } else {
#pragma unroll
                for (int rr = 0; rr < 2; rr++) {
                    float va = d[2 * rr], vb = d[2 * rr + 1];
                    bf16 ha = __float2bfloat16(va);
                    bf16 hb = __float2bfloat16(vb);
                    __nv_bfloat162 hv; hv.x = ha; hv.y = hb;
                    __nv_bfloat162 lv;
                    lv.x = __float2bfloat16(va - __bfloat162float(ha));
                    lv.y = __float2bfloat16(vb - __bfloat162float(hb));
                    const size_t o = cbase + (size_t)(r0 + 8 * rr) * ldc + c0;
                    *(uint32_t*)(Chi + o) = *(uint32_t*)&hv;
                    *(uint32_t*)(Clo + o) = *(uint32_t*)&lv;
                }
            }
        }
    }
}

// ---------------------------------------------------------------------------
__global__ void __launch_bounds__(256)
split_f32(const float* __restrict__ x, bf16* __restrict__ hi, bf16* __restrict__ lo, int n4)
{
    int i = blockIdx.x * 256 + threadIdx.x;
    if (i >= n4) return;
    float4 v = ((const float4*)x)[i];
    float f[4] = {v.x, v.y, v.z, v.w};
    bf16 h[4]; bf16 l[4];
#pragma unroll
    for (int j = 0; j < 4; j++) {
        h[j] = __float2bfloat16(f[j]);
        l[j] = __float2bfloat16(f[j] - __bfloat162float(h[j]));
    }
    ((uint2*)hi)[i] = *(uint2*)h;
    ((uint2*)lo)[i] = *(uint2*)l;
}

// ---------------------------------------------------------------------------
__global__ void __launch_bounds__(256)
transpose_split(const float* __restrict__ W, bf16* __restrict__ Thi, bf16* __restrict__ Tlo)
{
    __shared__ float t[32][33];
    const int bx = blockIdx.x * 32, by = blockIdx.y * 32;
    const int x = threadIdx.x, y = threadIdx.y;   // 32 x 8
#pragma unroll
    for (int i = 0; i < 32; i += 8)
        t[y + i][x] = W[(size_t)(by + y + i) * DIN + bx + x];
    __syncthreads();
#pragma unroll
    for (int i = 0; i < 32; i += 8) {
        float v = t[x][y + i];
        bf16 h = __float2bfloat16(v);
        bf16 l = __float2bfloat16(v - __bfloat162float(h));
        Thi[(size_t)(bx + y + i) * DIN + by + x] = h;
        Tlo[(size_t)(bx + y + i) * DIN + by + x] = l;
    }
}

// ---------------------------------------------------------------------------
// Softmax over k<=q of scale*S, emit split-bf16 P, zero-pad to 64 boundary
// ---------------------------------------------------------------------------
__global__ void __launch_bounds__(256)
softmax_split(const float* __restrict__ S, bf16* __restrict__ Phi, bf16* __restrict__ Plo,
              float scale)
{
    const int row = blockIdx.x;                // 0 .. B*SLEN-1
    const int q = row & (SLEN - 1);
    const float* p = S + (size_t)row * SLEN;
    const int L = q + 1;
    const int t = threadIdx.x;

    float v[8];
    float mx = -INFINITY;
#pragma unroll
    for (int i = 0; i < 8; i++) {
        int idx = t + i * 256;
        v[i] = (idx < L) ? p[idx] * scale : -INFINITY;
        mx = fmaxf(mx, v[i]);
    }

    __shared__ float redm[8];
    __shared__ float reds[8];

#pragma unroll
    for (int o = 16; o; o >>= 1) mx = fmaxf(mx, __shfl_xor_sync(0xFFFFFFFFu, mx, o));
    if ((t & 31) == 0) redm[t >> 5] = mx;
    __syncthreads();
    float m = redm[0];
#pragma unroll
    for (int i = 1; i < 8; i++) m = fmaxf(m, redm[i]);

    float s = 0.0f;
#pragma unroll
    for (int i = 0; i < 8; i++) {
        float e = __expf(v[i] - m);
        v[i] = e;
        s += e;
    }
#pragma unroll
    for (int o = 16; o; o >>= 1) s += __shfl_xor_sync(0xFFFFFFFFu, s, o);
    if ((t & 31) == 0) reds[t >> 5] = s;
    __syncthreads();
    float tot = 0.0f;
#pragma unroll
    for (int i = 0; i < 8; i++) tot += reds[i];
    const float inv = 1.0f / tot;

    bf16* ph = Phi + (size_t)row * SLEN;
    bf16* pl = Plo + (size_t)row * SLEN;
    const int pad = (L + 63) & ~63;
#pragma unroll
    for (int i = 0; i < 8; i++) {
        int idx = t + i * 256;
        if (idx < L) {
            float w = v[i] * inv;
            bf16 h = __float2bfloat16(w);
            ph[idx] = h;
            pl[idx] = __float2bfloat16(w - __bfloat162float(h));
        } else if (idx < pad) {
            ph[idx] = __float2bfloat16(0.0f);
            pl[idx] = __float2bfloat16(0.0f);
        }
    }
}

// ---------------------------------------------------------------------------
extern "C" void kernel_launch(void* const* d_in, const int* in_sizes, int n_in,
                              void* d_out, int out_size)
{
    const float* x  = (const float*)d_in[0];
    const float* Wq = (const float*)d_in[1];
    const float* Wk = (const float*)d_in[2];
    const float* Wv = (const float*)d_in[3];
    float* out = (float*)d_out;
    (void)in_sizes; (void)n_in; (void)out_size;

    cudaFuncSetAttribute(gemm3, cudaFuncAttributeMaxDynamicSharedMemorySize, SMEM_REQ);

    bf16 *Xhi, *Xlo, *WThi, *WTlo, *QKhi, *QKlo, *VThi, *VTlo, *Phi, *Plo;
    float *Sp;
    cudaGetSymbolAddress((void**)&Xhi, g_Xhi);
    cudaGetSymbolAddress((void**)&Xlo, g_Xlo);
    cudaGetSymbolAddress((void**)&WThi, g_WThi);
    cudaGetSymbolAddress((void**)&WTlo, g_WTlo);
    cudaGetSymbolAddress((void**)&QKhi, g_QKhi);
    cudaGetSymbolAddress((void**)&QKlo, g_QKlo);
    cudaGetSymbolAddress((void**)&VThi, g_VThi);
    cudaGetSymbolAddress((void**)&VTlo, g_VTlo);
    cudaGetSymbolAddress((void**)&Sp, g_S);
    cudaGetSymbolAddress((void**)&Phi, g_Phi);
    cudaGetSymbolAddress((void**)&Plo, g_Plo);

    const size_t WSTRIDE = (size_t)DIN * DIN;

    // 1) split x
    split_f32<<<(NTOK * DIN / 4) / 256, 256>>>(x, Xhi, Xlo, NTOK * DIN / 4);

    // 2) transpose + split the three weights ([0]=Wq^T, [1]=Wk^T contiguous)
    {
        dim3 g(DIN / 32, DIN / 32), b(32, 8);
        transpose_split<<<g, b>>>(Wq, WThi + 0 * WSTRIDE, WTlo + 0 * WSTRIDE);
        transpose_split<<<g, b>>>(Wk, WThi + 1 * WSTRIDE, WTlo + 1 * WSTRIDE);
        transpose_split<<<g, b>>>(Wv, WThi + 2 * WSTRIDE, WTlo + 2 * WSTRIDE);
    }

    // 3) merged QK projection: [8192 x 1024] @ [1024 x 2048] -> QK interleaved
    {
        dim3 g(2 * DIN / BN, NTOK / BM, 1);   // 16 x 128
        gemm3<<<g, 128, SMEM_REQ>>>(Xhi, Xlo, WThi, WTlo,
                                    DIN, DIN, DIN, 0, 0, 0,
                                    nullptr, QKhi, QKlo, 2 * DIN, 1, 0);
    }

    // 4) V^T = (x @ Wv)^T : A = Wv^T [1024x1024], B = X [8192x1024]
    {
        dim3 g(NTOK / BN, DIN / BM, 1);   // 64 x 16
        gemm3<<<g, 128, SMEM_REQ>>>(WThi + 2 * WSTRIDE, WTlo + 2 * WSTRIDE, Xhi, Xlo,
                                    DIN, DIN, DIN, 0, 0, 0,
                                    nullptr, VThi, VTlo, NTOK, 1, 0);
    }

    // 5) scores S[q][k] = Q . K per batch (unscaled), causal tile skip
    //    Q = QK cols [0,1024), K = QK cols [1024,2048), both ld = 2048
    {
        dim3 g(SLEN / BN, SLEN / BM, BATCH);   // 16 x 32 x 4
        gemm3<<<g, 128, SMEM_REQ>>>(QKhi, QKlo, QKhi + DIN, QKlo + DIN,
                                    DIN, 2 * DIN, 2 * DIN,
                                    (long long)SLEN * 2 * DIN, (long long)SLEN * 2 * DIN,
                                    (long long)SLEN * SLEN,
                                    Sp, nullptr, nullptr, SLEN, 0, 1);
    }

    // 6) softmax + split P
    softmax_split<<<BATCH * SLEN, 256>>>(Sp, Phi, Plo, 0.03125f);

    // 7) out = P @ V, causal k-bound + load-balanced by remap
    {
        dim3 g(DIN / BN, SLEN / BM, BATCH);    // 8 x 32 x 4
        gemm3<<<g, 128, SMEM_REQ>>>(Phi, Plo, VThi, VTlo,
                                    SLEN, SLEN, NTOK,
                                    (long long)SLEN * SLEN, (long long)SLEN,
                                    (long long)SLEN * DIN,
                                    out, nullptr, nullptr, DIN, 0, 3);
    }
}